// round 17
// baseline (speedup 1.0000x reference)
#include <cuda_runtime.h>
#include <cuda_fp16.h>
#include <cstdint>

#define DD 128
#define TT 64
#define NPOW 9           // A^0 .. A^8 (Taylor K=8; tail ~1e-5 relative)
#define BB 8192

// ---------------- device scratch (no allocs allowed) ----------------
// g_Bf[t] holds P_t TRANSPOSED: [n][k] n-major.
__device__ __align__(1024) __half g_Bf[TT][DD * DD];
__device__ __align__(1024) __half g_xh[BB * DD];        // x fp16
__device__ int g_gate = 0;    // prep completion counter (reset by last gemm CTA)
__device__ int g_fin = 0;     // gemm finisher counter

#define N_PREP 256
#define N_GEMM ((BB / 128) * (TT / 2))    // 2048

// ---------------- helpers ----------------
__device__ __forceinline__ uint32_t smem_u32(const void* p) {
    uint32_t a;
    asm("{ .reg .u64 t; cvta.to.shared.u64 t, %1; cvt.u32.u64 %0, t; }" : "=r"(a) : "l"(p));
    return a;
}
__device__ __forceinline__ void ldsm4(uint32_t* r, uint32_t a) {
    asm volatile("ldmatrix.sync.aligned.m8n8.x4.shared.b16 {%0,%1,%2,%3}, [%4];"
                 : "=r"(r[0]), "=r"(r[1]), "=r"(r[2]), "=r"(r[3]) : "r"(a));
}
__device__ __forceinline__ void mma16816(float* d, const uint32_t* a,
                                         uint32_t b0, uint32_t b1) {
    asm volatile(
        "mma.sync.aligned.m16n8k16.row.col.f32.f16.f16.f32 "
        "{%0,%1,%2,%3}, {%4,%5,%6,%7}, {%8,%9}, {%0,%1,%2,%3};"
        : "+f"(d[0]), "+f"(d[1]), "+f"(d[2]), "+f"(d[3])
        : "r"(a[0]), "r"(a[1]), "r"(a[2]), "r"(a[3]), "r"(b0), "r"(b1));
}
__device__ __forceinline__ void cp16(uint32_t dst, const void* src) {
    asm volatile("cp.async.cg.shared.global [%0], [%1], 16;" :: "r"(dst), "l"(src));
}
__device__ __forceinline__ void stcs2(float* p, float a, float b) {
    asm volatile("st.global.cs.v2.f32 [%0], {%1, %2};" :: "l"(p), "f"(a), "f"(b) : "memory");
}

// ---------------- layout constants ----------------
#define A_PAD 132
#define TC 2
#define A_STRIDE 272            // bytes: 128 fp16 + 8 pad
#define SM_A 0
#define SM_B0 (SM_A + 128 * A_STRIDE)         // 34816
#define SM_B1 (SM_B0 + 128 * A_STRIDE)        // 69632
#define SM_TOTAL (SM_B1 + 128 * A_STRIDE)     // 104448
// prep smem use (fits inside SM_TOTAL): 67584 + 4608 + 1024 = 73216

// ---------------- fused single kernel ----------------
// bids [0,128):    powers, 1 P-column per CTA, 2 threads/row (half-dots)
// bids [128,256):  x fp32 -> fp16
// bids [256,2304): GEMM, gated on g_gate == N_PREP
__global__ void __launch_bounds__(256, 2)
fused_kernel(const float* __restrict__ x, const float* __restrict__ W,
             float* __restrict__ out) {
    extern __shared__ __align__(16) char smem[];
    int tid = threadIdx.x, bid = blockIdx.x;

    if (bid < 128) {
        // ---- powers + combine ----
        float* sm = (float*)smem;
        float* Arow = sm;                        // [i][132]
        float* Mk = sm + 128 * A_PAD;            // [k][128]
        float* part = Mk + NPOW * 128;           // [128][2]

#pragma unroll
        for (int it = 0; it < 64; it++) {
            int idx = it * 256 + tid;
            int r = idx >> 7, c = idx & 127;
            Arow[r * A_PAD + c] = 0.01f * W[idx];
        }
        __syncthreads();

        int i = tid & 127, h = tid >> 7;
        int col = bid;

        float m[NPOW];
        m[0] = (i == col) ? 1.0f : 0.0f;
        m[1] = Arow[i * A_PAD + col];
        if (h == 0) Mk[1 * 128 + i] = m[1];
        __syncthreads();

        for (int k = 2; k < NPOW; k++) {
            const float* Mp = Mk + (k - 1) * 128;
            const float* ar = Arow + i * A_PAD + h * 64;
            const float* mp = Mp + h * 64;
            float s = 0.0f;
#pragma unroll
            for (int j = 0; j < 64; j += 4) {
                float4 a = *(const float4*)(ar + j);
                s += a.x * mp[j + 0];
                s += a.y * mp[j + 1];
                s += a.z * mp[j + 2];
                s += a.w * mp[j + 3];
            }
            part[i * 2 + h] = s;
            __syncthreads();
            m[k] = part[i * 2] + part[i * 2 + 1];
            if (h == 0) Mk[k * 128 + i] = m[k];
            __syncthreads();
        }

        int tbeg = h * 32, tend = tbeg + 32;
        for (int t = tbeg; t < tend; t++) {
            float tf = (float)t, cc = 1.0f, s = 0.0f;
#pragma unroll
            for (int k = 0; k < NPOW; k++) {
                s += cc * m[k];
                cc *= tf / (float)(k + 1);
            }
            g_Bf[t][col * DD + i] = __float2half_rn(s);
        }

        __threadfence();
        __syncthreads();
        if (tid == 0) atomicAdd(&g_gate, 1);     // arrive
        return;
    }

    if (bid < N_PREP) {
        // ---- x -> fp16 ----
        int cb = bid - 128;
        const float4* xs = (const float4*)(x + (size_t)cb * 8192);
        uint2* dst = (uint2*)(g_xh + (size_t)cb * 8192);
#pragma unroll
        for (int j = 0; j < 8; j++) {
            float4 v = xs[j * 256 + tid];
            __half2 h0 = __floats2half2_rn(v.x, v.y);
            __half2 h1 = __floats2half2_rn(v.z, v.w);
            dst[j * 256 + tid] = make_uint2(*(uint32_t*)&h0, *(uint32_t*)&h1);
        }
        __threadfence();
        __syncthreads();
        if (tid == 0) atomicAdd(&g_gate, 1);     // arrive
        return;
    }

    // ======================= GEMM path =======================
    int gid = bid - N_PREP;
    int rb = gid & 63;                 // 64 row-blocks
    int t0 = (gid >> 6) * TC;          // 32 t-blocks

    // gate: wait for all prep CTAs (wave-1 contains all of them -> no deadlock)
    if (tid == 0) {
        while (atomicAdd(&g_gate, 0) < N_PREP) __nanosleep(64);
    }
    __syncthreads();
    __threadfence();

    const __half* Ah = g_xh + (size_t)rb * 128 * DD;
    uint32_t sb = smem_u32(smem);

#pragma unroll
    for (int j = 0; j < 8; j++) {
        int idx = j * 256 + tid;
        int r = idx >> 4, cc = idx & 15;
        cp16(sb + SM_A + r * A_STRIDE + cc * 16, Ah + r * DD + cc * 8);
        cp16(sb + SM_B0 + r * A_STRIDE + cc * 16, g_Bf[t0] + r * DD + cc * 8);
    }
    asm volatile("cp.async.commit_group;" ::: "memory");

    int wid = tid >> 5, lane = tid & 31;
    int wm = wid & 3, wn = wid >> 2;
    uint32_t offA = (uint32_t)((wm * 32 + (lane & 15)) * A_STRIDE + (lane >> 4) * 16);
    uint32_t offB = (uint32_t)((wn * 64 + (lane & 7) + ((lane >> 1) & 8)) * A_STRIDE +
                               (lane & 8) * 2);
    uint32_t Ab = sb + SM_A + offA;
    uint32_t Bbuf[2] = {sb + SM_B0 + offB, sb + SM_B1 + offB};
    uint32_t Braw[2] = {sb + SM_B0, sb + SM_B1};

    int g = lane >> 2, q = lane & 3;
    size_t rowbase = (size_t)rb * 128 + wm * 32;

#pragma unroll
    for (int tt = 0; tt < TC; tt++) {
        if (tt < TC - 1) {
            const __half* Bn = g_Bf[t0 + tt + 1];
            uint32_t dst = Braw[(tt + 1) & 1];
#pragma unroll
            for (int j = 0; j < 8; j++) {
                int idx = j * 256 + tid;
                int r = idx >> 4, cc = idx & 15;
                cp16(dst + r * A_STRIDE + cc * 16, Bn + r * DD + cc * 8);
            }
            asm volatile("cp.async.commit_group;" ::: "memory");
            asm volatile("cp.async.wait_group 1;" ::: "memory");
        } else {
            asm volatile("cp.async.wait_group 0;" ::: "memory");
        }
        __syncthreads();

        uint32_t Bb = Bbuf[tt & 1];
        float acc[2][8][4];
#pragma unroll
        for (int i = 0; i < 2; i++)
#pragma unroll
            for (int j = 0; j < 8; j++)
#pragma unroll
                for (int k = 0; k < 4; k++) acc[i][j][k] = 0.0f;

#pragma unroll
        for (int ks = 0; ks < 8; ks++) {
            uint32_t a0[4], a1[4];
            ldsm4(a0, Ab + ks * 32);
            ldsm4(a1, Ab + ks * 32 + 16 * A_STRIDE);
#pragma unroll
            for (int j = 0; j < 4; j++) {    // n-groups of 16
                uint32_t b[4];
                ldsm4(b, Bb + j * 16 * A_STRIDE + ks * 32);
                mma16816(acc[0][2 * j],     a0, b[0], b[1]);
                mma16816(acc[0][2 * j + 1], a0, b[2], b[3]);
                mma16816(acc[1][2 * j],     a1, b[0], b[1]);
                mma16816(acc[1][2 * j + 1], a1, b[2], b[3]);
            }
        }

        int t = t0 + tt;
#pragma unroll
        for (int mt = 0; mt < 2; mt++) {
            size_t row = rowbase + mt * 16 + g;
#pragma unroll
            for (int nb = 0; nb < 8; nb++) {
                int col = wn * 64 + nb * 8 + q * 2;
                float* o = out + (row * TT + t) * DD + col;
                stcs2(o, acc[mt][nb][0], acc[mt][nb][1]);
                stcs2(o + (size_t)8 * TT * DD, acc[mt][nb][2], acc[mt][nb][3]);
            }
        }
        __syncthreads();
    }

    // replay-safe reset: last finishing gemm CTA clears the counters.
    // (all gemm CTAs have passed the gate; all prep arrivals happened before
    //  g_gate reached N_PREP)
    if (tid == 0) {
        int n = atomicAdd(&g_fin, 1);
        if (n == N_GEMM - 1) {
            g_gate = 0;
            __threadfence();
            g_fin = 0;
        }
    }
}

// ---------------- launch ----------------
extern "C" void kernel_launch(void* const* d_in, const int* in_sizes, int n_in,
                              void* d_out, int out_size) {
    const float* x = (const float*)d_in[0];
    const float* W = (const float*)d_in[1];
    float* out = (float*)d_out;

    cudaFuncSetAttribute(fused_kernel, cudaFuncAttributeMaxDynamicSharedMemorySize, SM_TOTAL);
    fused_kernel<<<N_PREP + N_GEMM, 256, SM_TOTAL>>>(x, W, out);
}